// round 10
// baseline (speedup 1.0000x reference)
#include <cuda_runtime.h>
#include <cuda_fp16.h>
#include <stdint.h>
#include <math.h>

#define NQ     2048
#define MREF   50000
#define DD     128
#define NPAD   50048              // 391 * 128
#define NTILES 391
#define CHUNK  64
#define NCHUNK (NPAD / CHUNK)     // 782
#define NCP2   784                // padded stride for g_gmaxT rows (196 float4)
#define S      136                // padded smem row stride in halfs (272 B)
#define CANDMAX 4096
#define CLISTMAX 128
#define EPS2   2.0e-3f            // margin: |HMMA dot - recomputed dot| bound (generous)
#define HBINS  256
#define HRANGE 0.5f
#define HW     (HRANGE / HBINS)   // bin width ~1.95e-3

// ---------------- static device scratch (allocation-free) ----------------
__device__ __align__(16) __half g_a[NQ * DD];             // normalized queries, fp16
__device__ __align__(16) __half g_b[NPAD * DD];           // normalized refs, zero-padded
__device__ __align__(16) float g_gmaxT[(size_t)NQ * NCP2]; // per-query per-64chunk max (6.4 MB)

__device__ __forceinline__ uint32_t smem_u32(const void* p) {
    uint32_t a;
    asm("{ .reg .u64 t; cvta.to.shared.u64 t, %1; cvt.u32.u64 %0, t; }" : "=r"(a) : "l"(p));
    return a;
}

// ---------------- 1) normalize all rows -> fp16 (warp per row, fused) ----------------
__global__ void normalize_all(const float* __restrict__ z, const float* __restrict__ ref) {
    const int wid = threadIdx.x >> 5, lane = threadIdx.x & 31;
    const float* in;
    __half* outp;
    int row;
    if (blockIdx.x < NQ / 8) {
        row = blockIdx.x * 8 + wid;
        in = z; outp = g_a;
    } else {
        row = (blockIdx.x - NQ / 8) * 8 + wid;
        if (row >= MREF) return;
        in = ref; outp = g_b;
    }
    float4 v = *(const float4*)&in[row * DD + lane * 4];
    float s = v.x * v.x + v.y * v.y + v.z * v.z + v.w * v.w;
    #pragma unroll
    for (int o = 16; o > 0; o >>= 1) s += __shfl_xor_sync(0xffffffffu, s, o);
    float inv = rsqrtf(s);
    __half2 h0 = __floats2half2_rn(v.x * inv, v.y * inv);
    __half2 h1 = __floats2half2_rn(v.z * inv, v.w * inv);
    __half2* dst = (__half2*)(outp + row * DD + lane * 4);
    dst[0] = h0; dst[1] = h1;
}

// ---------------- 2) HMMA GEMM -> per-64-chunk max only ----------------
// grid (391, 16), 256 threads (8 warps, 2x4 warp grid), warp tile 64x32, K=128 resident
__global__ void __launch_bounds__(256, 2) knn_gemm() {
    extern __shared__ __align__(16) __half sm[];
    __half* Asm = sm;                    // [128][S]
    __half* Bsm = sm + 128 * S;          // [128][S]
    __shared__ float sgm[128][4];        // staged per-row warp maxima

    const int tid  = threadIdx.x;
    const int wid  = tid >> 5, lane = tid & 31;
    const int n0   = blockIdx.x * 128, m0 = blockIdx.y * 128;
    const int wm   = wid & 1;            // 0..1 (M)
    const int wn   = wid >> 1;           // 0..3 (N)

    {
        const uint4* a = (const uint4*)(g_a + (size_t)m0 * DD);
        const uint4* b = (const uint4*)(g_b + (size_t)n0 * DD);
        #pragma unroll
        for (int it = 0; it < 8; it++) {
            int c = tid + it * 256;
            int r = c >> 4, q = c & 15;
            *(uint4*)&Asm[r * S + q * 8] = a[c];
            *(uint4*)&Bsm[r * S + q * 8] = b[c];
        }
    }
    __syncthreads();

    float acc[4][4][4];
    #pragma unroll
    for (int i = 0; i < 4; i++)
        #pragma unroll
        for (int j = 0; j < 4; j++)
            #pragma unroll
            for (int x = 0; x < 4; x++) acc[i][j][x] = 0.0f;

    const uint32_t a_base = smem_u32(Asm);
    const uint32_t b_base = smem_u32(Bsm);
    const uint32_t aoff = ((uint32_t)((wm * 64 + (lane & 15)) * S + (lane >> 4) * 8)) * 2;
    const uint32_t boff = ((uint32_t)((wn * 32 + (lane & 15)) * S + (lane >> 4) * 8)) * 2;

    #pragma unroll
    for (int ks = 0; ks < 8; ks++) {
        const uint32_t kb = (uint32_t)(ks * 16) * 2;
        uint32_t af[4][4];
        #pragma unroll
        for (int mi = 0; mi < 4; mi++) {
            uint32_t addr = a_base + aoff + (uint32_t)(mi * 16 * S) * 2 + kb;
            asm volatile("ldmatrix.sync.aligned.m8n8.x4.shared.b16 {%0,%1,%2,%3}, [%4];"
                         : "=r"(af[mi][0]), "=r"(af[mi][1]), "=r"(af[mi][2]), "=r"(af[mi][3])
                         : "r"(addr));
        }
        uint32_t bf[2][4];
        #pragma unroll
        for (int np = 0; np < 2; np++) {
            uint32_t addr = b_base + boff + (uint32_t)(np * 16 * S) * 2 + kb;
            asm volatile("ldmatrix.sync.aligned.m8n8.x4.shared.b16 {%0,%1,%2,%3}, [%4];"
                         : "=r"(bf[np][0]), "=r"(bf[np][1]), "=r"(bf[np][2]), "=r"(bf[np][3])
                         : "r"(addr));
        }
        #pragma unroll
        for (int mi = 0; mi < 4; mi++) {
            #pragma unroll
            for (int ni = 0; ni < 4; ni++) {
                uint32_t b0 = bf[ni >> 1][ni & 1];
                uint32_t b1 = bf[ni >> 1][(ni & 1) + 2];
                asm volatile(
                    "mma.sync.aligned.m16n8k16.row.col.f32.f16.f16.f32 "
                    "{%0,%1,%2,%3}, {%4,%5,%6,%7}, {%8,%9}, {%0,%1,%2,%3};"
                    : "+f"(acc[mi][ni][0]), "+f"(acc[mi][ni][1]),
                      "+f"(acc[mi][ni][2]), "+f"(acc[mi][ni][3])
                    : "r"(af[mi][0]), "r"(af[mi][1]), "r"(af[mi][2]), "r"(af[mi][3]),
                      "r"(b0), "r"(b1));
            }
        }
    }

    const int g  = lane >> 2;
    const int tc = (lane & 3) * 2;
    const bool tail = (blockIdx.x == NTILES - 1);

    #pragma unroll
    for (int mi = 0; mi < 4; mi++) {
        const int lr = wm * 64 + mi * 16 + g;
        float mx0 = -3.0e38f, mx1 = -3.0e38f;
        #pragma unroll
        for (int ni = 0; ni < 4; ni++) {
            const int col = n0 + wn * 32 + ni * 8 + tc;
            float v0 = acc[mi][ni][0], v1 = acc[mi][ni][1];
            float w0 = acc[mi][ni][2], w1 = acc[mi][ni][3];
            if (tail) {
                if (col     >= MREF) { v0 = -3.0e38f; w0 = -3.0e38f; }
                if (col + 1 >= MREF) { v1 = -3.0e38f; w1 = -3.0e38f; }
            }
            mx0 = fmaxf(mx0, fmaxf(v0, v1));
            mx1 = fmaxf(mx1, fmaxf(w0, w1));
        }
        mx0 = fmaxf(mx0, __shfl_xor_sync(0xffffffffu, mx0, 1));
        mx0 = fmaxf(mx0, __shfl_xor_sync(0xffffffffu, mx0, 2));
        mx1 = fmaxf(mx1, __shfl_xor_sync(0xffffffffu, mx1, 1));
        mx1 = fmaxf(mx1, __shfl_xor_sync(0xffffffffu, mx1, 2));
        if ((lane & 3) == 0) {
            sgm[lr][wn]     = mx0;
            sgm[lr + 8][wn] = mx1;
        }
    }
    __syncthreads();
    if (tid < 128) {
        float4 vv = *(float4*)sgm[tid];
        float2 o = make_float2(fmaxf(vv.x, vv.y), fmaxf(vv.z, vv.w));
        *(float2*)&g_gmaxT[(size_t)(m0 + tid) * NCP2 + blockIdx.x * 2] = o;
    }
}

// ---------------- 3) register-resident histogram selection (1 block / query) ----------------
__global__ void __launch_bounds__(256, 6) phase2_select(const int* __restrict__ kptr,
                                                        float* __restrict__ out) {
    const int q = blockIdx.x;
    const int t = threadIdx.x;
    const int lane = t & 31;
    const int wid  = t >> 5;
    int kk = kptr[0] + 1;
    kk = kk < 1 ? 1 : (kk > 16 ? 16 : kk);

    __shared__ __align__(16) float aq[DD];
    __shared__ int   hist[HBINS];
    __shared__ float cand[CANDMAX];
    __shared__ int   clist[CLISTMAX];
    __shared__ float red[8];
    __shared__ int   ncc, n_cand, s_fb;
    __shared__ float s_thr, s_res;

    // ---- 4 chunk maxima per thread, register-resident ----
    const int cbase = t * 4;
    float v0 = -3.4e38f, v1 = -3.4e38f, v2 = -3.4e38f, v3 = -3.4e38f;
    if (t < NCP2 / 4) {
        float4 r4 = *(const float4*)&g_gmaxT[(size_t)q * NCP2 + cbase];
        v0 = (cbase + 0 < NCHUNK) ? r4.x : -3.4e38f;
        v1 = (cbase + 1 < NCHUNK) ? r4.y : -3.4e38f;
        v2 = (cbase + 2 < NCHUNK) ? r4.z : -3.4e38f;
        v3 = (cbase + 3 < NCHUNK) ? r4.w : -3.4e38f;
    }
    if (t < DD) aq[t] = __half2float(g_a[q * DD + t]);
    hist[t] = 0;
    if (t == 0) { ncc = 0; n_cand = 0; s_fb = 0; }
    __syncthreads();

    // ---- block max ----
    float bm = fmaxf(fmaxf(v0, v1), fmaxf(v2, v3));
    #pragma unroll
    for (int o = 16; o > 0; o >>= 1) bm = fmaxf(bm, __shfl_xor_sync(0xffffffffu, bm, o));
    if (lane == 0) red[wid] = bm;
    __syncthreads();
    float M = red[0];
    #pragma unroll
    for (int w = 1; w < 8; w++) M = fmaxf(M, red[w]);

    // ---- histogram of (M - v); -inf pads land beyond HBINS automatically ----
    const float invW = 1.0f / HW;
    {
        int b0 = (int)((M - v0) * invW); if (b0 >= 0 && b0 < HBINS) atomicAdd(&hist[b0], 1);
        int b1 = (int)((M - v1) * invW); if (b1 >= 0 && b1 < HBINS) atomicAdd(&hist[b1], 1);
        int b2 = (int)((M - v2) * invW); if (b2 >= 0 && b2 < HBINS) atomicAdd(&hist[b2], 1);
        int b3 = (int)((M - v3) * invW); if (b3 >= 0 && b3 < HBINS) atomicAdd(&hist[b3], 1);
    }
    __syncthreads();

    // ---- warp0: suffix scan -> first bin with cum >= kk ----
    if (t < 32) {
        int cnt[8], seg = 0;
        #pragma unroll
        for (int i = 0; i < 8; i++) { cnt[i] = hist[t * 8 + i]; seg += cnt[i]; }
        int inc = seg;
        #pragma unroll
        for (int o = 1; o < 32; o <<= 1) {
            int x = __shfl_up_sync(0xffffffffu, inc, o);
            if (lane >= o) inc += x;
        }
        int run = inc - seg;
        int bstar = 1 << 30;
        #pragma unroll
        for (int i = 0; i < 8; i++) {
            run += cnt[i];
            if (run >= kk && bstar == (1 << 30)) bstar = t * 8 + i;
        }
        #pragma unroll
        for (int o = 16; o > 0; o >>= 1) {
            int ob = __shfl_xor_sync(0xffffffffu, bstar, o);
            bstar = ob < bstar ? ob : bstar;
        }
        if (t == 0) {
            if (bstar >= HBINS) s_fb = 1;
            else s_thr = M - (float)(bstar + 1) * HW - EPS2;
        }
    }
    __syncthreads();

    bool fallback = (s_fb != 0);
    const float thr = s_thr;

    // ---- candidate chunk list (from registers) ----
    if (!fallback) {
        if (v0 >= thr) { int p = atomicAdd(&ncc, 1); if (p < CLISTMAX) clist[p] = cbase + 0; }
        if (v1 >= thr) { int p = atomicAdd(&ncc, 1); if (p < CLISTMAX) clist[p] = cbase + 1; }
        if (v2 >= thr) { int p = atomicAdd(&ncc, 1); if (p < CLISTMAX) clist[p] = cbase + 2; }
        if (v3 >= thr) { int p = atomicAdd(&ncc, 1); if (p < CLISTMAX) clist[p] = cbase + 3; }
        __syncthreads();
        if (ncc > CLISTMAX) fallback = true;
    }

    // ---- warp-cooperative recompute of candidate dots (coalesced 8B/lane rows) ----
    if (!fallback) {
        const int total = ncc * CHUNK;
        const float4 aqv = *(const float4*)&aq[lane * 4];
        for (int base = wid * 4; base < total; base += 32) {
            float d[4];
            #pragma unroll
            for (int u = 0; u < 4; u++) {
                int idx = base + u;
                bool ok = idx < total;
                int c   = ok ? clist[idx >> 6] : 0;
                int ref = c * CHUNK + (idx & 63);
                ok = ok && (ref < MREF);
                float dot = 0.0f;
                if (ok) {
                    uint2 raw = *((const uint2*)(g_b + (size_t)ref * DD) + lane);
                    float2 f0 = __half22float2(*(__half2*)&raw.x);
                    float2 f1 = __half22float2(*(__half2*)&raw.y);
                    dot = aqv.x * f0.x + aqv.y * f0.y + aqv.z * f1.x + aqv.w * f1.y;
                }
                d[u] = dot;
            }
            #pragma unroll
            for (int o = 16; o > 0; o >>= 1) {
                #pragma unroll
                for (int u = 0; u < 4; u++)
                    d[u] += __shfl_xor_sync(0xffffffffu, d[u], o);
            }
            if (lane < 4) {
                int idx = base + lane;
                if (idx < total) {
                    int c   = clist[idx >> 6];
                    int ref = c * CHUNK + (idx & 63);
                    if (ref < MREF && d[lane] >= thr) {
                        int p = atomicAdd(&n_cand, 1);
                        if (p < CANDMAX) cand[p] = d[lane];
                    }
                }
            }
        }
        __syncthreads();
        if (n_cand > CANDMAX || n_cand < kk) fallback = true;
    }

    int nc = n_cand;
    if (fallback) {
        // ---- exhaustive recompute, per-thread top-16 (always correct, rare) ----
        __syncthreads();
        float top[16];
        #pragma unroll
        for (int i = 0; i < 16; i++) top[i] = -3.4e38f;
        for (int ref = t; ref < MREF; ref += 256) {
            const __half2* b = (const __half2*)(g_b + (size_t)ref * DD);
            float dot = 0.0f;
            #pragma unroll
            for (int d = 0; d < 64; d++) {
                float2 bb = __half22float2(b[d]);
                dot += aq[2 * d] * bb.x + aq[2 * d + 1] * bb.y;
            }
            if (dot > top[15]) {
                top[15] = dot;
                #pragma unroll
                for (int i = 15; i > 0; i--) {
                    if (top[i] > top[i - 1]) { float tv = top[i-1]; top[i-1] = top[i]; top[i] = tv; }
                }
            }
        }
        __syncthreads();
        #pragma unroll
        for (int i = 0; i < 16; i++) cand[t * 16 + i] = top[i];
        __syncthreads();
        nc = CANDMAX;
    }

    // ---- warp0: exact kk-th largest via per-lane sorted lists + k-way shuffle merge ----
    if (t < 32) {
        float top[16];
        #pragma unroll
        for (int i = 0; i < 16; i++) top[i] = -3.4e38f;
        for (int c = t; c < nc; c += 32) {
            float v = cand[c];
            if (v > top[15]) {
                top[15] = v;
                #pragma unroll
                for (int i = 15; i > 0; i--) {
                    if (top[i] > top[i - 1]) { float tv = top[i-1]; top[i-1] = top[i]; top[i] = tv; }
                }
            }
        }
        float kth = -3.4e38f;
        for (int it = 0; it < kk; it++) {
            float v = top[0]; int bl = t;
            #pragma unroll
            for (int o = 16; o > 0; o >>= 1) {
                float ov = __shfl_xor_sync(0xffffffffu, v, o);
                int   ol = __shfl_xor_sync(0xffffffffu, bl, o);
                if (ov > v || (ov == v && ol < bl)) { v = ov; bl = ol; }
            }
            if (t == bl) {
                #pragma unroll
                for (int i = 0; i < 15; i++) top[i] = top[i + 1];
                top[15] = -3.4e38f;
            }
            kth = v;
        }
        if (t == 0) s_res = kth;
    }
    __syncthreads();

    if (t == 0) out[q] = sqrtf(fmaxf(2.0f - 2.0f * s_res, 1e-12f));
}

// ---------------- launch ----------------
extern "C" void kernel_launch(void* const* d_in, const int* in_sizes, int n_in,
                              void* d_out, int out_size) {
    const float* z    = (const float*)d_in[0];   // [2048,128]
    const float* ref  = (const float*)d_in[1];   // [50000,128]
    const int*   kptr = (const int*)d_in[2];     // scalar k
    float*       out  = (float*)d_out;           // [2048]

    const int smem_bytes = 2 * 128 * S * (int)sizeof(__half);   // 69632
    cudaFuncSetAttribute(knn_gemm, cudaFuncAttributeMaxDynamicSharedMemorySize, smem_bytes);

    normalize_all<<<NQ / 8 + (MREF + 7) / 8, 256>>>(z, ref);

    dim3 grid(NTILES, 16);
    knn_gemm<<<grid, 256, smem_bytes>>>();

    phase2_select<<<NQ, 256>>>(kptr, out);
}

// round 11
// speedup vs baseline: 1.2689x; 1.2689x over previous
#include <cuda_runtime.h>
#include <cuda_fp16.h>
#include <stdint.h>
#include <math.h>

#define NQ     2048
#define MREF   50000
#define DD     128
#define NPAD   50048              // 391 * 128
#define NTILES 391
#define CHUNK  32
#define NCHUNK (NPAD / CHUNK)     // 1564
#define NCP    1568               // padded stride for g_gmaxT rows
#define S      136                // padded smem row stride in halfs (272 B)
#define CANDMAX 4096
#define CLISTMAX 256
#define EPS2   2.0e-3f            // margin: |HMMA dot - recomputed dot| bound (generous)
#define HBINS  256
#define HRANGE 0.5f
#define HW     (HRANGE / HBINS)   // bin width ~1.95e-3

// ---------------- static device scratch (allocation-free) ----------------
__device__ __align__(16) __half g_a[NQ * DD];             // normalized queries, fp16
__device__ __align__(16) __half g_b[NPAD * DD];           // normalized refs, zero-padded
__device__ float g_gmaxT[(size_t)NQ * NCP];               // per-query per-chunk max (12.8 MB)

__device__ __forceinline__ uint32_t smem_u32(const void* p) {
    uint32_t a;
    asm("{ .reg .u64 t; cvta.to.shared.u64 t, %1; cvt.u32.u64 %0, t; }" : "=r"(a) : "l"(p));
    return a;
}

// ---------------- 1) normalize all rows -> fp16 (warp per row, fused) ----------------
__global__ void normalize_all(const float* __restrict__ z, const float* __restrict__ ref) {
    const int wid = threadIdx.x >> 5, lane = threadIdx.x & 31;
    const float* in;
    __half* outp;
    int row;
    if (blockIdx.x < NQ / 8) {
        row = blockIdx.x * 8 + wid;
        in = z; outp = g_a;
    } else {
        row = (blockIdx.x - NQ / 8) * 8 + wid;
        if (row >= MREF) return;
        in = ref; outp = g_b;
    }
    float4 v = *(const float4*)&in[row * DD + lane * 4];
    float s = v.x * v.x + v.y * v.y + v.z * v.z + v.w * v.w;
    #pragma unroll
    for (int o = 16; o > 0; o >>= 1) s += __shfl_xor_sync(0xffffffffu, s, o);
    float inv = rsqrtf(s);
    __half2 h0 = __floats2half2_rn(v.x * inv, v.y * inv);
    __half2 h1 = __floats2half2_rn(v.z * inv, v.w * inv);
    __half2* dst = (__half2*)(outp + row * DD + lane * 4);
    dst[0] = h0; dst[1] = h1;
}

// ---------------- 2) HMMA GEMM -> per-chunk max only ----------------
// grid (391, 16), 256 threads (8 warps, 2x4 warp grid), warp tile 64x32, K=128 resident
__global__ void __launch_bounds__(256, 2) knn_gemm() {
    extern __shared__ __align__(16) __half sm[];
    __half* Asm = sm;                    // [128][S]
    __half* Bsm = sm + 128 * S;          // [128][S]
    __shared__ float sgm[128][4];        // staged per-row chunk maxima

    const int tid  = threadIdx.x;
    const int wid  = tid >> 5, lane = tid & 31;
    const int n0   = blockIdx.x * 128, m0 = blockIdx.y * 128;
    const int wm   = wid & 1;            // 0..1 (M)
    const int wn   = wid >> 1;           // 0..3 (N)

    {
        const uint4* a = (const uint4*)(g_a + (size_t)m0 * DD);
        const uint4* b = (const uint4*)(g_b + (size_t)n0 * DD);
        #pragma unroll
        for (int it = 0; it < 8; it++) {
            int c = tid + it * 256;
            int r = c >> 4, q = c & 15;
            *(uint4*)&Asm[r * S + q * 8] = a[c];
            *(uint4*)&Bsm[r * S + q * 8] = b[c];
        }
    }
    __syncthreads();

    float acc[4][4][4];
    #pragma unroll
    for (int i = 0; i < 4; i++)
        #pragma unroll
        for (int j = 0; j < 4; j++)
            #pragma unroll
            for (int x = 0; x < 4; x++) acc[i][j][x] = 0.0f;

    const uint32_t a_base = smem_u32(Asm);
    const uint32_t b_base = smem_u32(Bsm);
    const uint32_t aoff = ((uint32_t)((wm * 64 + (lane & 15)) * S + (lane >> 4) * 8)) * 2;
    const uint32_t boff = ((uint32_t)((wn * 32 + (lane & 15)) * S + (lane >> 4) * 8)) * 2;

    #pragma unroll
    for (int ks = 0; ks < 8; ks++) {
        const uint32_t kb = (uint32_t)(ks * 16) * 2;
        uint32_t af[4][4];
        #pragma unroll
        for (int mi = 0; mi < 4; mi++) {
            uint32_t addr = a_base + aoff + (uint32_t)(mi * 16 * S) * 2 + kb;
            asm volatile("ldmatrix.sync.aligned.m8n8.x4.shared.b16 {%0,%1,%2,%3}, [%4];"
                         : "=r"(af[mi][0]), "=r"(af[mi][1]), "=r"(af[mi][2]), "=r"(af[mi][3])
                         : "r"(addr));
        }
        uint32_t bf[2][4];
        #pragma unroll
        for (int np = 0; np < 2; np++) {
            uint32_t addr = b_base + boff + (uint32_t)(np * 16 * S) * 2 + kb;
            asm volatile("ldmatrix.sync.aligned.m8n8.x4.shared.b16 {%0,%1,%2,%3}, [%4];"
                         : "=r"(bf[np][0]), "=r"(bf[np][1]), "=r"(bf[np][2]), "=r"(bf[np][3])
                         : "r"(addr));
        }
        #pragma unroll
        for (int mi = 0; mi < 4; mi++) {
            #pragma unroll
            for (int ni = 0; ni < 4; ni++) {
                uint32_t b0 = bf[ni >> 1][ni & 1];
                uint32_t b1 = bf[ni >> 1][(ni & 1) + 2];
                asm volatile(
                    "mma.sync.aligned.m16n8k16.row.col.f32.f16.f16.f32 "
                    "{%0,%1,%2,%3}, {%4,%5,%6,%7}, {%8,%9}, {%0,%1,%2,%3};"
                    : "+f"(acc[mi][ni][0]), "+f"(acc[mi][ni][1]),
                      "+f"(acc[mi][ni][2]), "+f"(acc[mi][ni][3])
                    : "r"(af[mi][0]), "r"(af[mi][1]), "r"(af[mi][2]), "r"(af[mi][3]),
                      "r"(b0), "r"(b1));
            }
        }
    }

    const int g  = lane >> 2;
    const int tc = (lane & 3) * 2;
    const bool tail = (blockIdx.x == NTILES - 1);

    #pragma unroll
    for (int mi = 0; mi < 4; mi++) {
        const int lr = wm * 64 + mi * 16 + g;
        float mx0 = -3.0e38f, mx1 = -3.0e38f;
        #pragma unroll
        for (int ni = 0; ni < 4; ni++) {
            const int col = n0 + wn * 32 + ni * 8 + tc;
            float v0 = acc[mi][ni][0], v1 = acc[mi][ni][1];
            float w0 = acc[mi][ni][2], w1 = acc[mi][ni][3];
            if (tail) {
                if (col     >= MREF) { v0 = -3.0e38f; w0 = -3.0e38f; }
                if (col + 1 >= MREF) { v1 = -3.0e38f; w1 = -3.0e38f; }
            }
            mx0 = fmaxf(mx0, fmaxf(v0, v1));
            mx1 = fmaxf(mx1, fmaxf(w0, w1));
        }
        mx0 = fmaxf(mx0, __shfl_xor_sync(0xffffffffu, mx0, 1));
        mx0 = fmaxf(mx0, __shfl_xor_sync(0xffffffffu, mx0, 2));
        mx1 = fmaxf(mx1, __shfl_xor_sync(0xffffffffu, mx1, 1));
        mx1 = fmaxf(mx1, __shfl_xor_sync(0xffffffffu, mx1, 2));
        if ((lane & 3) == 0) {
            sgm[lr][wn]     = mx0;
            sgm[lr + 8][wn] = mx1;
        }
    }
    __syncthreads();
    if (tid < 128) {
        float4 v = *(float4*)sgm[tid];
        *(float4*)&g_gmaxT[(size_t)(m0 + tid) * NCP + blockIdx.x * 4] = v;
    }
}

// ---------------- 3) histogram-threshold exact selection (1 block / query) ----------------
__global__ void __launch_bounds__(256, 6) phase2_select(const int* __restrict__ kptr,
                                                        float* __restrict__ out) {
    const int q = blockIdx.x;
    const int t = threadIdx.x;
    const int lane = t & 31;
    const int wid  = t >> 5;
    int kk = kptr[0] + 1;
    kk = kk < 1 ? 1 : (kk > 16 ? 16 : kk);

    __shared__ float smax[NCHUNK];
    __shared__ __align__(16) float aq[DD];
    __shared__ int   hist[HBINS];
    __shared__ float cand[CANDMAX];
    __shared__ int   clist[CLISTMAX];
    __shared__ float red[8];
    __shared__ int   ncc, n_cand, s_fb;
    __shared__ float s_thr, s_res;

    for (int c = t; c < NCHUNK; c += 256) smax[c] = g_gmaxT[(size_t)q * NCP + c];
    if (t < DD) aq[t] = __half2float(g_a[q * DD + t]);
    hist[t] = 0;
    if (t == 0) { ncc = 0; n_cand = 0; s_fb = 0; }
    __syncthreads();

    // ---- block max of chunk maxima ----
    float bm = -3.4e38f;
    for (int c = t; c < NCHUNK; c += 256) bm = fmaxf(bm, smax[c]);
    #pragma unroll
    for (int o = 16; o > 0; o >>= 1) bm = fmaxf(bm, __shfl_xor_sync(0xffffffffu, bm, o));
    if (lane == 0) red[wid] = bm;
    __syncthreads();
    float M = red[0];
    #pragma unroll
    for (int w = 1; w < 8; w++) M = fmaxf(M, red[w]);

    // ---- histogram of (M - v) over [0, HRANGE) ----
    const float invW = 1.0f / HW;
    for (int c = t; c < NCHUNK; c += 256) {
        float d = M - smax[c];
        int b = (int)(d * invW);
        if (b < 0) b = 0;
        if (b < HBINS) atomicAdd(&hist[b], 1);
    }
    __syncthreads();

    // ---- warp0: suffix scan -> first bin with cum >= kk ----
    if (t < 32) {
        int cnt[8], seg = 0;
        #pragma unroll
        for (int i = 0; i < 8; i++) { cnt[i] = hist[t * 8 + i]; seg += cnt[i]; }
        int inc = seg;
        #pragma unroll
        for (int o = 1; o < 32; o <<= 1) {
            int x = __shfl_up_sync(0xffffffffu, inc, o);
            if (lane >= o) inc += x;
        }
        int run = inc - seg;
        int bstar = 1 << 30;
        #pragma unroll
        for (int i = 0; i < 8; i++) {
            run += cnt[i];
            if (run >= kk && bstar == (1 << 30)) bstar = t * 8 + i;
        }
        #pragma unroll
        for (int o = 16; o > 0; o >>= 1) {
            int ob = __shfl_xor_sync(0xffffffffu, bstar, o);
            bstar = ob < bstar ? ob : bstar;
        }
        if (t == 0) {
            if (bstar >= HBINS) s_fb = 1;
            else s_thr = M - (float)(bstar + 1) * HW - EPS2;
        }
    }
    __syncthreads();

    bool fallback = (s_fb != 0);
    const float thr = s_thr;

    // ---- candidate chunk list ----
    if (!fallback) {
        for (int c = t; c < NCHUNK; c += 256) {
            if (smax[c] >= thr) {
                int p = atomicAdd(&ncc, 1);
                if (p < CLISTMAX) clist[p] = c;
            }
        }
        __syncthreads();
        if (ncc > CLISTMAX) fallback = true;
    }

    // ---- warp-cooperative recompute of candidate dots (coalesced 8B/lane rows) ----
    if (!fallback) {
        const int total = ncc * CHUNK;
        const float4 aqv = *(const float4*)&aq[lane * 4];
        for (int base = wid * 4; base < total; base += 32) {
            float d[4];
            #pragma unroll
            for (int u = 0; u < 4; u++) {
                int idx = base + u;
                bool ok = idx < total;
                int c   = ok ? clist[idx >> 5] : 0;
                int ref = c * CHUNK + (idx & 31);
                ok = ok && (ref < MREF);
                float dot = 0.0f;
                if (ok) {
                    uint2 raw = *((const uint2*)(g_b + (size_t)ref * DD) + lane);
                    float2 f0 = __half22float2(*(__half2*)&raw.x);
                    float2 f1 = __half22float2(*(__half2*)&raw.y);
                    dot = aqv.x * f0.x + aqv.y * f0.y + aqv.z * f1.x + aqv.w * f1.y;
                }
                d[u] = dot;
            }
            #pragma unroll
            for (int o = 16; o > 0; o >>= 1) {
                #pragma unroll
                for (int u = 0; u < 4; u++)
                    d[u] += __shfl_xor_sync(0xffffffffu, d[u], o);
            }
            if (lane < 4) {
                int idx = base + lane;
                if (idx < total) {
                    int c   = clist[idx >> 5];
                    int ref = c * CHUNK + (idx & 31);
                    if (ref < MREF && d[lane] >= thr) {
                        int p = atomicAdd(&n_cand, 1);
                        if (p < CANDMAX) cand[p] = d[lane];
                    }
                }
            }
        }
        __syncthreads();
        if (n_cand > CANDMAX || n_cand < kk) fallback = true;
    }

    int nc = n_cand;
    if (fallback) {
        // ---- exhaustive recompute, per-thread top-16 (always correct, rare) ----
        __syncthreads();
        float top[16];
        #pragma unroll
        for (int i = 0; i < 16; i++) top[i] = -3.4e38f;
        for (int ref = t; ref < MREF; ref += 256) {
            const __half2* b = (const __half2*)(g_b + (size_t)ref * DD);
            float dot = 0.0f;
            #pragma unroll
            for (int d = 0; d < 64; d++) {
                float2 bb = __half22float2(b[d]);
                dot += aq[2 * d] * bb.x + aq[2 * d + 1] * bb.y;
            }
            if (dot > top[15]) {
                top[15] = dot;
                #pragma unroll
                for (int i = 15; i > 0; i--) {
                    if (top[i] > top[i - 1]) { float tv = top[i-1]; top[i-1] = top[i]; top[i] = tv; }
                }
            }
        }
        __syncthreads();
        #pragma unroll
        for (int i = 0; i < 16; i++) cand[t * 16 + i] = top[i];
        __syncthreads();
        nc = CANDMAX;
    }

    // ---- warp0: exact kk-th largest via per-lane sorted lists + k-way shuffle merge ----
    if (t < 32) {
        float top[16];
        #pragma unroll
        for (int i = 0; i < 16; i++) top[i] = -3.4e38f;
        for (int c = t; c < nc; c += 32) {
            float v = cand[c];
            if (v > top[15]) {
                top[15] = v;
                #pragma unroll
                for (int i = 15; i > 0; i--) {
                    if (top[i] > top[i - 1]) { float tv = top[i-1]; top[i-1] = top[i]; top[i] = tv; }
                }
            }
        }
        float kth = -3.4e38f;
        for (int it = 0; it < kk; it++) {
            float v = top[0]; int bl = t;
            #pragma unroll
            for (int o = 16; o > 0; o >>= 1) {
                float ov = __shfl_xor_sync(0xffffffffu, v, o);
                int   ol = __shfl_xor_sync(0xffffffffu, bl, o);
                if (ov > v || (ov == v && ol < bl)) { v = ov; bl = ol; }
            }
            if (t == bl) {
                #pragma unroll
                for (int i = 0; i < 15; i++) top[i] = top[i + 1];
                top[15] = -3.4e38f;
            }
            kth = v;
        }
        if (t == 0) s_res = kth;
    }
    __syncthreads();

    if (t == 0) out[q] = sqrtf(fmaxf(2.0f - 2.0f * s_res, 1e-12f));
}

// ---------------- launch ----------------
extern "C" void kernel_launch(void* const* d_in, const int* in_sizes, int n_in,
                              void* d_out, int out_size) {
    const float* z    = (const float*)d_in[0];   // [2048,128]
    const float* ref  = (const float*)d_in[1];   // [50000,128]
    const int*   kptr = (const int*)d_in[2];     // scalar k
    float*       out  = (float*)d_out;           // [2048]

    const int smem_bytes = 2 * 128 * S * (int)sizeof(__half);   // 69632
    cudaFuncSetAttribute(knn_gemm, cudaFuncAttributeMaxDynamicSharedMemorySize, smem_bytes);

    normalize_all<<<NQ / 8 + (MREF + 7) / 8, 256>>>(z, ref);

    dim3 grid(NTILES, 16);
    knn_gemm<<<grid, 256, smem_bytes>>>();

    phase2_select<<<NQ, 256>>>(kptr, out);
}